// round 15
// baseline (speedup 1.0000x reference)
#include <cuda_runtime.h>
#include <cstdint>

// Problem constants (fixed by setup_inputs)
#define B_    4
#define NC    4096      // coarse points per batch
#define MF    16384     // fine points per batch
#define CIN   384
#define COUT  192
#define NTOT  (B_*NC)   // 16384
#define MTOT  (B_*MF)   // 65536

// Scratch (static device globals; allocation-free)
__device__ float g_h[NTOT * COUT];      // branch-2 features at coarse points
__device__ int   g_idx[MTOT * 3];       // 3-NN indices (global coarse index)
__device__ float g_wgt[MTOT * 3];       // 3-NN inverse-distance weights
__device__ float g_stat_f[NTOT * 2];    // per-row (mu, rstd) feats
__device__ float g_stat_s[MTOT * 2];    // per-row (mu, rstd) support_feats
__device__ float g_w2p[CIN * COUT];     // gamma-folded weights [k][n]
__device__ float g_w1p[COUT * COUT];
__device__ float g_b2p[COUT];           // beta-folded biases
__device__ float g_b1p[COUT];

// ---------------------------------------------------------------------------
// Per-row LN statistics: one warp per row -> (mu, rstd)
// ---------------------------------------------------------------------------
template<int C>
__global__ void stats_kernel(const float* __restrict__ x, float* __restrict__ stat, int rows)
{
    int warp = (blockIdx.x * blockDim.x + threadIdx.x) >> 5;
    if (warp >= rows) return;
    int lane = threadIdx.x & 31;
    const float* xr = x + (long)warp * C;
    float s = 0.f, ss = 0.f;
#pragma unroll
    for (int i = 0; i < C / 32; i++) {
        float v = xr[lane + i * 32];
        s += v;
        ss += v * v;
    }
#pragma unroll
    for (int o = 16; o; o >>= 1) {
        s  += __shfl_xor_sync(0xffffffffu, s,  o);
        ss += __shfl_xor_sync(0xffffffffu, ss, o);
    }
    if (lane == 0) {
        float mu  = s * (1.0f / C);
        float var = ss * (1.0f / C) - mu * mu;
        stat[warp * 2 + 0] = mu;
        stat[warp * 2 + 1] = rsqrtf(var + 1e-5f);
    }
}

// ---------------------------------------------------------------------------
// Fold LN gamma into W, LN beta into bias.
// ---------------------------------------------------------------------------
__global__ void prep_kernel(const float* __restrict__ w2, const float* __restrict__ ln2_g,
                            const float* __restrict__ ln2_b, const float* __restrict__ b2,
                            const float* __restrict__ w1, const float* __restrict__ ln1_g,
                            const float* __restrict__ ln1_b, const float* __restrict__ b1)
{
    int bid = blockIdx.x;
    int n = threadIdx.x;             // 0..191
    if (bid < CIN) {
        g_w2p[bid * COUT + n] = ln2_g[bid] * w2[bid * COUT + n];
    } else if (bid < CIN + COUT) {
        int k = bid - CIN;
        g_w1p[k * COUT + n] = ln1_g[k] * w1[k * COUT + n];
    } else if (bid == CIN + COUT) {
        float s = b2[n];
        for (int k = 0; k < CIN; k++) s = fmaf(ln2_b[k], w2[k * COUT + n], s);
        g_b2p[n] = s;
    } else {
        float s = b1[n];
        for (int k = 0; k < COUT; k++) s = fmaf(ln1_b[k], w1[k * COUT + n], s);
        g_b1p[n] = s;
    }
}

// ---------------------------------------------------------------------------
// Brute-force 3-NN. 2 queries per thread, 512 queries per block.
// ---------------------------------------------------------------------------
__global__ void knn_kernel(const float* __restrict__ cxyz, const float* __restrict__ qxyz)
{
    extern __shared__ char smem_c[];
    float* sx = (float*)smem_c;
    float* sy = sx + NC;
    float* sz = sx + 2 * NC;

    int bidx  = blockIdx.x >> 5;
    int chunk = blockIdx.x & 31;
    const float* cb = cxyz + (long)bidx * NC * 3;
    for (int i = threadIdx.x; i < NC; i += 256) {
        sx[i] = cb[i * 3 + 0];
        sy[i] = cb[i * 3 + 1];
        sz[i] = cb[i * 3 + 2];
    }
    __syncthreads();

    int qA = bidx * MF + chunk * 512 + threadIdx.x;
    int qB = qA + 256;
    float ax = qxyz[qA * 3 + 0], ay = qxyz[qA * 3 + 1], az = qxyz[qA * 3 + 2];
    float bx = qxyz[qB * 3 + 0], by = qxyz[qB * 3 + 1], bz = qxyz[qB * 3 + 2];

    float a0 = 1e30f, a1 = 1e30f, a2 = 1e30f; int ai0 = 0, ai1 = 0, ai2 = 0;
    float c0 = 1e30f, c1 = 1e30f, c2 = 1e30f; int ci0 = 0, ci1 = 0, ci2 = 0;

#pragma unroll 8
    for (int j = 0; j < NC; j++) {
        float px = sx[j], py = sy[j], pz = sz[j];
        {
            float dx = ax - px, dy = ay - py, dz = az - pz;
            float d = fmaf(dz, dz, fmaf(dy, dy, dx * dx));
            if (d < a2) {
                if (d < a1) {
                    a2 = a1; ai2 = ai1;
                    if (d < a0) { a1 = a0; ai1 = ai0; a0 = d; ai0 = j; }
                    else        { a1 = d;  ai1 = j; }
                } else { a2 = d; ai2 = j; }
            }
        }
        {
            float dx = bx - px, dy = by - py, dz = bz - pz;
            float d = fmaf(dz, dz, fmaf(dy, dy, dx * dx));
            if (d < c2) {
                if (d < c1) {
                    c2 = c1; ci2 = ci1;
                    if (d < c0) { c1 = c0; ci1 = ci0; c0 = d; ci0 = j; }
                    else        { c1 = d;  ci1 = j; }
                } else { c2 = d; ci2 = j; }
            }
        }
    }

    {
        float r0 = 1.0f / (sqrtf(a0) + 1e-8f);
        float r1 = 1.0f / (sqrtf(a1) + 1e-8f);
        float r2 = 1.0f / (sqrtf(a2) + 1e-8f);
        float rs = 1.0f / (r0 + r1 + r2);
        g_idx[qA * 3 + 0] = bidx * NC + ai0;
        g_idx[qA * 3 + 1] = bidx * NC + ai1;
        g_idx[qA * 3 + 2] = bidx * NC + ai2;
        g_wgt[qA * 3 + 0] = r0 * rs;
        g_wgt[qA * 3 + 1] = r1 * rs;
        g_wgt[qA * 3 + 2] = r2 * rs;
    }
    {
        float r0 = 1.0f / (sqrtf(c0) + 1e-8f);
        float r1 = 1.0f / (sqrtf(c1) + 1e-8f);
        float r2 = 1.0f / (sqrtf(c2) + 1e-8f);
        float rs = 1.0f / (r0 + r1 + r2);
        g_idx[qB * 3 + 0] = bidx * NC + ci0;
        g_idx[qB * 3 + 1] = bidx * NC + ci1;
        g_idx[qB * 3 + 2] = bidx * NC + ci2;
        g_wgt[qB * 3 + 0] = r0 * rs;
        g_wgt[qB * 3 + 1] = r1 * rs;
        g_wgt[qB * 3 + 2] = r2 * rs;
    }
}

// ---------------------------------------------------------------------------
// Fused LN + GEMM (R2 champion with BK=32):
//   C[M,192] = ((A - mu) * rstd) @ W' + b'   (+ optional 3-NN interp)
// BM=128, BN=64, BK=32, 256 threads, 8x4 microtile, double-buffered dynamic
// smem (50 KB), register prefetch, ONE __syncthreads per 32 k-steps.
// ---------------------------------------------------------------------------
#define AS_STRIDE (32 * 132)            // floats per A stage
#define BS_STRIDE (32 * 68)             // floats per B stage
#define AS_TOT    (2 * AS_STRIDE)
#define GSMEM     ((AS_TOT + 2 * BS_STRIDE) * 4)   // 51200 bytes

template<int K, bool INTERP>
__global__ __launch_bounds__(256)
void gemm_kernel(const float* __restrict__ A, const float* __restrict__ stat,
                 const float* __restrict__ W, const float* __restrict__ bias,
                 float* __restrict__ C)
{
    constexpr int KT = K / 32;
    extern __shared__ float smem_f[];
    // As(s,k,m) = smem_f[s*AS_STRIDE + k*132 + m]
    // Bs(s,k,n) = smem_f[AS_TOT + s*BS_STRIDE + k*68 + n]

    int t  = threadIdx.x;
    int tx = t & 15, ty = t >> 4;
    int m0 = blockIdx.y * 128;
    int n0 = blockIdx.x * 64;

    // A loader: thread -> (row = t>>1, 16-col group = (t&1)*16), 4 float4
    int arow   = t >> 1;
    int acol16 = (t & 1) * 16;
    const float* Arow = A + (long)(m0 + arow) * K;
    float mu   = stat[(m0 + arow) * 2 + 0];
    float rstd = stat[(m0 + arow) * 2 + 1];

    // B loader: 32k x 64n = 512 float4; item i -> k=i>>4, nq=(i&15)*4; items t, t+256
    int bk0 = t >> 4;
    int bn0 = (t & 15) * 4;

    float4 pa[4], pb[2];

    // --- prologue: stage 0
#pragma unroll
    for (int q = 0; q < 4; q++) pa[q] = *(const float4*)(Arow + acol16 + q * 4);
    pb[0] = *(const float4*)(W + (long)bk0 * COUT + n0 + bn0);
    pb[1] = *(const float4*)(W + (long)(bk0 + 16) * COUT + n0 + bn0);
    {
        float* As0 = smem_f;
#pragma unroll
        for (int q = 0; q < 4; q++) {
            float vv[4] = {pa[q].x, pa[q].y, pa[q].z, pa[q].w};
#pragma unroll
            for (int j = 0; j < 4; j++)
                As0[(acol16 + q * 4 + j) * 132 + arow] = (vv[j] - mu) * rstd;
        }
        float* Bs0 = smem_f + AS_TOT;
        *(float4*)&Bs0[bk0 * 68 + bn0]        = pb[0];
        *(float4*)&Bs0[(bk0 + 16) * 68 + bn0] = pb[1];
    }
    __syncthreads();

    float acc[8][4] = {};
    int s = 0;

#pragma unroll 1
    for (int kt = 0; kt < KT; kt++) {
        int k1 = (kt + 1) * 32;
        const bool more = (kt + 1 < KT);
        if (more) {
#pragma unroll
            for (int q = 0; q < 4; q++) pa[q] = *(const float4*)(Arow + k1 + acol16 + q * 4);
            pb[0] = *(const float4*)(W + (long)(k1 + bk0) * COUT + n0 + bn0);
            pb[1] = *(const float4*)(W + (long)(k1 + bk0 + 16) * COUT + n0 + bn0);
        }

        const float* Asb = smem_f + s * AS_STRIDE;
        const float* Bsb = smem_f + AS_TOT + s * BS_STRIDE;
#pragma unroll
        for (int k = 0; k < 32; k++) {
            float4 a0 = *(const float4*)&Asb[k * 132 + ty * 8];
            float4 a1 = *(const float4*)&Asb[k * 132 + ty * 8 + 4];
            float4 b  = *(const float4*)&Bsb[k * 68 + tx * 4];
            float ar[8] = {a0.x, a0.y, a0.z, a0.w, a1.x, a1.y, a1.z, a1.w};
            float br[4] = {b.x, b.y, b.z, b.w};
#pragma unroll
            for (int i = 0; i < 8; i++)
#pragma unroll
                for (int j = 0; j < 4; j++)
                    acc[i][j] = fmaf(ar[i], br[j], acc[i][j]);
        }

        if (more) {
            int ns = s ^ 1;
            float* Asn = smem_f + ns * AS_STRIDE;
            float* Bsn = smem_f + AS_TOT + ns * BS_STRIDE;
            __syncthreads();   // ensure stage ns no longer being read (prev iter)
#pragma unroll
            for (int q = 0; q < 4; q++) {
                float vv[4] = {pa[q].x, pa[q].y, pa[q].z, pa[q].w};
#pragma unroll
                for (int j = 0; j < 4; j++)
                    Asn[(acol16 + q * 4 + j) * 132 + arow] = (vv[j] - mu) * rstd;
            }
            *(float4*)&Bsn[bk0 * 68 + bn0]        = pb[0];
            *(float4*)&Bsn[(bk0 + 16) * 68 + bn0] = pb[1];
            __syncthreads();
            s = ns;
        }
    }

    // --- epilogue
    float bb[4];
#pragma unroll
    for (int j = 0; j < 4; j++) bb[j] = bias[n0 + tx * 4 + j];

#pragma unroll
    for (int i = 0; i < 8; i++) {
        int row = m0 + ty * 8 + i;
        float o0 = acc[i][0] + bb[0], o1 = acc[i][1] + bb[1];
        float o2 = acc[i][2] + bb[2], o3 = acc[i][3] + bb[3];
        if (INTERP) {
            int   j0 = g_idx[row * 3 + 0], j1 = g_idx[row * 3 + 1], j2 = g_idx[row * 3 + 2];
            float w0 = g_wgt[row * 3 + 0], w1 = g_wgt[row * 3 + 1], w2 = g_wgt[row * 3 + 2];
            int coff = n0 + tx * 4;
            float4 h0 = *(const float4*)(g_h + (long)j0 * COUT + coff);
            float4 h1 = *(const float4*)(g_h + (long)j1 * COUT + coff);
            float4 h2 = *(const float4*)(g_h + (long)j2 * COUT + coff);
            o0 += w0 * h0.x + w1 * h1.x + w2 * h2.x;
            o1 += w0 * h0.y + w1 * h1.y + w2 * h2.y;
            o2 += w0 * h0.z + w1 * h1.z + w2 * h2.z;
            o3 += w0 * h0.w + w1 * h1.w + w2 * h2.w;
        }
        *(float4*)(C + (long)row * COUT + n0 + tx * 4) = make_float4(o0, o1, o2, o3);
    }
}

// ---------------------------------------------------------------------------
// Tail: copy support_xyz and support_offset (value-cast to float) into d_out
// ---------------------------------------------------------------------------
__global__ void tail_kernel(const float* __restrict__ sxyz, const int* __restrict__ soff,
                            float* __restrict__ out)
{
    int i = blockIdx.x * 256 + threadIdx.x;
    if (i < MTOT * 3) out[MTOT * COUT + i] = sxyz[i];
    if (i < B_)       out[MTOT * COUT + MTOT * 3 + i] = (float)soff[i];
}

// ---------------------------------------------------------------------------
extern "C" void kernel_launch(void* const* d_in, const int* in_sizes, int n_in,
                              void* d_out, int out_size)
{
    const float* feats  = (const float*)d_in[0];
    const float* xyz    = (const float*)d_in[1];
    const float* sxyz   = (const float*)d_in[2];
    const float* sfeats = (const float*)d_in[3];
    const int*   soff   = (const int*)  d_in[5];
    const float* ln1_g  = (const float*)d_in[6];
    const float* ln1_b  = (const float*)d_in[7];
    const float* w1     = (const float*)d_in[8];
    const float* b1     = (const float*)d_in[9];
    const float* ln2_g  = (const float*)d_in[10];
    const float* ln2_b  = (const float*)d_in[11];
    const float* w2     = (const float*)d_in[12];
    const float* b2     = (const float*)d_in[13];
    float* out = (float*)d_out;

    static cudaStream_t s2 = nullptr, s3 = nullptr;
    static cudaEvent_t ev_fork = nullptr, ev_j2 = nullptr, ev_j3 = nullptr, ev_prep = nullptr;
    static bool attr_done = false;
    if (!s2) {
        cudaStreamCreateWithFlags(&s2, cudaStreamNonBlocking);
        cudaStreamCreateWithFlags(&s3, cudaStreamNonBlocking);
        cudaEventCreateWithFlags(&ev_fork, cudaEventDisableTiming);
        cudaEventCreateWithFlags(&ev_j2, cudaEventDisableTiming);
        cudaEventCreateWithFlags(&ev_j3, cudaEventDisableTiming);
        cudaEventCreateWithFlags(&ev_prep, cudaEventDisableTiming);
    }
    if (!attr_done) {
        cudaFuncSetAttribute(gemm_kernel<CIN,  false>, cudaFuncAttributeMaxDynamicSharedMemorySize, GSMEM);
        cudaFuncSetAttribute(gemm_kernel<COUT, true >, cudaFuncAttributeMaxDynamicSharedMemorySize, GSMEM);
        attr_done = true;
    }

    float *p_stat_f, *p_stat_s, *p_h, *p_w2p, *p_w1p, *p_b2p, *p_b1p;
    cudaGetSymbolAddress((void**)&p_stat_f, g_stat_f);
    cudaGetSymbolAddress((void**)&p_stat_s, g_stat_s);
    cudaGetSymbolAddress((void**)&p_h,      g_h);
    cudaGetSymbolAddress((void**)&p_w2p,    g_w2p);
    cudaGetSymbolAddress((void**)&p_w1p,    g_w1p);
    cudaGetSymbolAddress((void**)&p_b2p,    g_b2p);
    cudaGetSymbolAddress((void**)&p_b1p,    g_b1p);

    // fork
    cudaEventRecord(ev_fork, 0);
    cudaStreamWaitEvent(s2, ev_fork, 0);
    cudaStreamWaitEvent(s3, ev_fork, 0);

    // s2: kNN + tail (independent of GEMM chain)
    knn_kernel<<<MTOT / 512, 256, 3 * NC * sizeof(float), s2>>>(xyz, sxyz);
    tail_kernel<<<(MTOT * 3 + 255) / 256, 256, 0, s2>>>(sxyz, soff, out);
    cudaEventRecord(ev_j2, s2);

    // s3: weight prep, then stats for branch 1
    prep_kernel<<<CIN + COUT + 2, COUT, 0, s3>>>(w2, ln2_g, ln2_b, b2, w1, ln1_g, ln1_b, b1);
    cudaEventRecord(ev_prep, s3);
    stats_kernel<COUT><<<MTOT / 8, 256, 0, s3>>>(sfeats, p_stat_s, MTOT);
    cudaEventRecord(ev_j3, s3);

    // main: stats_f -> gemm2
    stats_kernel<CIN><<<NTOT / 8, 256>>>(feats, p_stat_f, NTOT);
    cudaStreamWaitEvent(0, ev_prep, 0);
    {
        dim3 grid(COUT / 64, NTOT / 128);
        gemm_kernel<CIN, false><<<grid, 256, GSMEM>>>(feats, p_stat_f, p_w2p, p_b2p, p_h);
    }

    // join, then gemm1 with fused interp epilogue
    cudaStreamWaitEvent(0, ev_j2, 0);
    cudaStreamWaitEvent(0, ev_j3, 0);
    {
        dim3 grid(COUT / 64, MTOT / 128);
        gemm_kernel<COUT, true><<<grid, 256, GSMEM>>>(sfeats, p_stat_s, p_w1p, p_b1p, out);
    }
}

// round 16
// speedup vs baseline: 1.3847x; 1.3847x over previous
#include <cuda_runtime.h>
#include <cstdint>

// Problem constants (fixed by setup_inputs)
#define B_    4
#define NC    4096      // coarse points per batch
#define MF    16384     // fine points per batch
#define CIN   384
#define COUT  192
#define NTOT  (B_*NC)   // 16384
#define MTOT  (B_*MF)   // 65536

// Scratch (static device globals; allocation-free)
__device__ float g_h[NTOT * COUT];      // branch-2 features at coarse points
__device__ int   g_idx[MTOT * 3];       // 3-NN indices (global coarse index)
__device__ float g_wgt[MTOT * 3];       // 3-NN normalized inverse-distance weights
__device__ float g_stat_f[NTOT * 2];    // per-row (mu, rstd) for feats
__device__ float g_stat_s[MTOT * 2];    // per-row (mu, rstd) for support_feats
__device__ float g_w2p[CIN * COUT];     // gamma-folded weights
__device__ float g_w1p[COUT * COUT];
__device__ float g_b2p[COUT];           // beta-folded biases
__device__ float g_b1p[COUT];

// ---------------------------------------------------------------------------
// Per-row LN statistics: one warp per row -> (mu, rstd)
// ---------------------------------------------------------------------------
template<int C>
__global__ void stats_kernel(const float* __restrict__ x, float* __restrict__ stat, int rows)
{
    int warp = (blockIdx.x * blockDim.x + threadIdx.x) >> 5;
    if (warp >= rows) return;
    int lane = threadIdx.x & 31;
    const float* xr = x + (long)warp * C;
    float s = 0.f, ss = 0.f;
#pragma unroll
    for (int i = 0; i < C / 32; i++) {
        float v = xr[lane + i * 32];
        s += v;
        ss += v * v;
    }
#pragma unroll
    for (int o = 16; o; o >>= 1) {
        s  += __shfl_xor_sync(0xffffffffu, s,  o);
        ss += __shfl_xor_sync(0xffffffffu, ss, o);
    }
    if (lane == 0) {
        float mu  = s * (1.0f / C);
        float var = ss * (1.0f / C) - mu * mu;
        stat[warp * 2 + 0] = mu;
        stat[warp * 2 + 1] = rsqrtf(var + 1e-5f);
    }
}

// ---------------------------------------------------------------------------
// Fold LN gamma into W, LN beta into bias:
//   W'[k][n] = g[k] * W[k][n]         b'[n] = b[n] + sum_k beta[k] * W[k][n]
// grid = CIN + COUT + 2 blocks of 192 threads
// ---------------------------------------------------------------------------
__global__ void prep_kernel(const float* __restrict__ w2, const float* __restrict__ ln2_g,
                            const float* __restrict__ ln2_b, const float* __restrict__ b2,
                            const float* __restrict__ w1, const float* __restrict__ ln1_g,
                            const float* __restrict__ ln1_b, const float* __restrict__ b1)
{
    int bid = blockIdx.x;
    int n = threadIdx.x;             // 0..191
    if (bid < CIN) {
        g_w2p[bid * COUT + n] = ln2_g[bid] * w2[bid * COUT + n];
    } else if (bid < CIN + COUT) {
        int k = bid - CIN;
        g_w1p[k * COUT + n] = ln1_g[k] * w1[k * COUT + n];
    } else if (bid == CIN + COUT) {
        float s = b2[n];
        for (int k = 0; k < CIN; k++) s = fmaf(ln2_b[k], w2[k * COUT + n], s);
        g_b2p[n] = s;
    } else {
        float s = b1[n];
        for (int k = 0; k < COUT; k++) s = fmaf(ln1_b[k], w1[k * COUT + n], s);
        g_b1p[n] = s;
    }
}

// ---------------------------------------------------------------------------
// Brute-force 3-NN per batch segment. Coarse xyz in shared (SoA, 48KB).
// ---------------------------------------------------------------------------
__global__ void knn_kernel(const float* __restrict__ cxyz,   // [NTOT,3] coarse
                           const float* __restrict__ qxyz)   // [MTOT,3] fine
{
    extern __shared__ float smem[];
    float* sx = smem;
    float* sy = smem + NC;
    float* sz = smem + 2 * NC;

    int bidx  = blockIdx.x >> 6;
    int chunk = blockIdx.x & 63;
    const float* cb = cxyz + (long)bidx * NC * 3;
    for (int i = threadIdx.x; i < NC; i += 256) {
        sx[i] = cb[i * 3 + 0];
        sy[i] = cb[i * 3 + 1];
        sz[i] = cb[i * 3 + 2];
    }
    __syncthreads();

    int q = bidx * MF + chunk * 256 + threadIdx.x;
    float qx = qxyz[q * 3 + 0], qy = qxyz[q * 3 + 1], qz = qxyz[q * 3 + 2];

    float b0 = 1e30f, b1 = 1e30f, b2 = 1e30f;
    int   i0 = 0, i1 = 0, i2 = 0;

#pragma unroll 8
    for (int j = 0; j < NC; j++) {
        float dx = qx - sx[j];
        float dy = qy - sy[j];
        float dz = qz - sz[j];
        float d  = fmaf(dz, dz, fmaf(dy, dy, dx * dx));
        if (d < b2) {
            if (d < b1) {
                b2 = b1; i2 = i1;
                if (d < b0) { b1 = b0; i1 = i0; b0 = d; i0 = j; }
                else        { b1 = d;  i1 = j; }
            } else { b2 = d; i2 = j; }
        }
    }

    float r0 = 1.0f / (sqrtf(b0) + 1e-8f);
    float r1 = 1.0f / (sqrtf(b1) + 1e-8f);
    float r2 = 1.0f / (sqrtf(b2) + 1e-8f);
    float rs = 1.0f / (r0 + r1 + r2);

    g_idx[q * 3 + 0] = bidx * NC + i0;
    g_idx[q * 3 + 1] = bidx * NC + i1;
    g_idx[q * 3 + 2] = bidx * NC + i2;
    g_wgt[q * 3 + 0] = r0 * rs;
    g_wgt[q * 3 + 1] = r1 * rs;
    g_wgt[q * 3 + 2] = r2 * rs;
}

// ---------------------------------------------------------------------------
// Fused LN-normalize + GEMM (R2 champion, verbatim):
//   C[M,192] = ((A - mu) * rstd) @ W' + b'   (+ optional 3-NN interp gather)
// BM=128, BN=64, BK=16, 256 threads, 8x4 microtile, double-buffered smem.
// ---------------------------------------------------------------------------
template<int K, bool INTERP>
__global__ __launch_bounds__(256)
void gemm_kernel(const float* __restrict__ A, const float* __restrict__ stat,
                 const float* __restrict__ W, const float* __restrict__ bias,
                 float* __restrict__ C)
{
    constexpr int KT = K / 16;
    __shared__ float As[2][16][132];   // [stage][k][m] (transposed, padded)
    __shared__ float Bs[2][16][64];    // [stage][k][n]

    int t  = threadIdx.x;
    int tx = t & 15, ty = t >> 4;
    int m0 = blockIdx.y * 128;
    int n0 = blockIdx.x * 64;

    // A loader: thread -> (row, 8-col group); 2 float4 = full 32B sector pair
    int arow  = t >> 1;
    int acol8 = (t & 1) * 8;
    const float* Arow = A + (long)(m0 + arow) * K;
    float mu   = stat[(m0 + arow) * 2 + 0];
    float rstd = stat[(m0 + arow) * 2 + 1];

    // B loader
    int brow = t >> 4;
    int bcol = (t & 15) * 4;

    float4 pa0, pa1, pb;

    // prologue: tile 0
    pa0 = *(const float4*)(Arow + acol8);
    pa1 = *(const float4*)(Arow + acol8 + 4);
    pb  = *(const float4*)(W + (long)brow * COUT + n0 + bcol);
    As[0][acol8 + 0][arow] = (pa0.x - mu) * rstd;
    As[0][acol8 + 1][arow] = (pa0.y - mu) * rstd;
    As[0][acol8 + 2][arow] = (pa0.z - mu) * rstd;
    As[0][acol8 + 3][arow] = (pa0.w - mu) * rstd;
    As[0][acol8 + 4][arow] = (pa1.x - mu) * rstd;
    As[0][acol8 + 5][arow] = (pa1.y - mu) * rstd;
    As[0][acol8 + 6][arow] = (pa1.z - mu) * rstd;
    As[0][acol8 + 7][arow] = (pa1.w - mu) * rstd;
    *(float4*)&Bs[0][brow][bcol] = pb;
    __syncthreads();

    float acc[8][4] = {};
    int s = 0;

#pragma unroll 1
    for (int kt = 0; kt < KT; kt++) {
        int k0n = (kt + 1) * 16;
        if (kt + 1 < KT) {
            pa0 = *(const float4*)(Arow + k0n + acol8);
            pa1 = *(const float4*)(Arow + k0n + acol8 + 4);
            pb  = *(const float4*)(W + (long)(k0n + brow) * COUT + n0 + bcol);
        }
#pragma unroll
        for (int k = 0; k < 16; k++) {
            float4 a0 = *(const float4*)&As[s][k][ty * 8];
            float4 a1 = *(const float4*)&As[s][k][ty * 8 + 4];
            float4 b  = *(const float4*)&Bs[s][k][tx * 4];
            float ar[8] = {a0.x, a0.y, a0.z, a0.w, a1.x, a1.y, a1.z, a1.w};
            float br[4] = {b.x, b.y, b.z, b.w};
#pragma unroll
            for (int i = 0; i < 8; i++)
#pragma unroll
                for (int j = 0; j < 4; j++)
                    acc[i][j] = fmaf(ar[i], br[j], acc[i][j]);
        }
        if (kt + 1 < KT) {
            int ns = s ^ 1;
            As[ns][acol8 + 0][arow] = (pa0.x - mu) * rstd;
            As[ns][acol8 + 1][arow] = (pa0.y - mu) * rstd;
            As[ns][acol8 + 2][arow] = (pa0.z - mu) * rstd;
            As[ns][acol8 + 3][arow] = (pa0.w - mu) * rstd;
            As[ns][acol8 + 4][arow] = (pa1.x - mu) * rstd;
            As[ns][acol8 + 5][arow] = (pa1.y - mu) * rstd;
            As[ns][acol8 + 6][arow] = (pa1.z - mu) * rstd;
            As[ns][acol8 + 7][arow] = (pa1.w - mu) * rstd;
            *(float4*)&Bs[ns][brow][bcol] = pb;
            __syncthreads();
            s = ns;
        }
    }

    float bb[4];
#pragma unroll
    for (int j = 0; j < 4; j++) bb[j] = bias[n0 + tx * 4 + j];

#pragma unroll
    for (int i = 0; i < 8; i++) {
        int row = m0 + ty * 8 + i;
        float add0 = bb[0], add1 = bb[1], add2 = bb[2], add3 = bb[3];
        if (INTERP) {
            int   j0 = g_idx[row * 3 + 0], j1 = g_idx[row * 3 + 1], j2 = g_idx[row * 3 + 2];
            float w0 = g_wgt[row * 3 + 0], w1 = g_wgt[row * 3 + 1], w2 = g_wgt[row * 3 + 2];
            int coff = n0 + tx * 4;
            float4 h0 = *(const float4*)(g_h + (long)j0 * COUT + coff);
            float4 h1 = *(const float4*)(g_h + (long)j1 * COUT + coff);
            float4 h2 = *(const float4*)(g_h + (long)j2 * COUT + coff);
            add0 += w0 * h0.x + w1 * h1.x + w2 * h2.x;
            add1 += w0 * h0.y + w1 * h1.y + w2 * h2.y;
            add2 += w0 * h0.z + w1 * h1.z + w2 * h2.z;
            add3 += w0 * h0.w + w1 * h1.w + w2 * h2.w;
        }
        float4 o = make_float4(acc[i][0] + add0, acc[i][1] + add1,
                               acc[i][2] + add2, acc[i][3] + add3);
        *(float4*)(C + (long)row * COUT + n0 + tx * 4) = o;
    }
}

// ---------------------------------------------------------------------------
// Tail: copy support_xyz and support_offset (value-cast to float) into d_out
// ---------------------------------------------------------------------------
__global__ void tail_kernel(const float* __restrict__ sxyz, const int* __restrict__ soff,
                            float* __restrict__ out)
{
    int i = blockIdx.x * 256 + threadIdx.x;
    if (i < MTOT * 3) out[MTOT * COUT + i] = sxyz[i];
    if (i < B_)       out[MTOT * COUT + MTOT * 3 + i] = (float)soff[i];
}

// ---------------------------------------------------------------------------
extern "C" void kernel_launch(void* const* d_in, const int* in_sizes, int n_in,
                              void* d_out, int out_size)
{
    const float* feats  = (const float*)d_in[0];
    const float* xyz    = (const float*)d_in[1];
    const float* sxyz   = (const float*)d_in[2];
    const float* sfeats = (const float*)d_in[3];
    const int*   soff   = (const int*)  d_in[5];
    const float* ln1_g  = (const float*)d_in[6];
    const float* ln1_b  = (const float*)d_in[7];
    const float* w1     = (const float*)d_in[8];
    const float* b1     = (const float*)d_in[9];
    const float* ln2_g  = (const float*)d_in[10];
    const float* ln2_b  = (const float*)d_in[11];
    const float* w2     = (const float*)d_in[12];
    const float* b2     = (const float*)d_in[13];
    float* out = (float*)d_out;

    static cudaStream_t s2 = nullptr, s3 = nullptr;
    static cudaEvent_t ev_fork = nullptr, ev_j2 = nullptr, ev_j3 = nullptr, ev_prep = nullptr;
    if (!s2) {
        cudaStreamCreateWithFlags(&s2, cudaStreamNonBlocking);
        cudaStreamCreateWithFlags(&s3, cudaStreamNonBlocking);
        cudaEventCreateWithFlags(&ev_fork, cudaEventDisableTiming);
        cudaEventCreateWithFlags(&ev_j2, cudaEventDisableTiming);
        cudaEventCreateWithFlags(&ev_j3, cudaEventDisableTiming);
        cudaEventCreateWithFlags(&ev_prep, cudaEventDisableTiming);
    }

    float *p_stat_f, *p_stat_s, *p_h, *p_w2p, *p_w1p, *p_b2p, *p_b1p;
    cudaGetSymbolAddress((void**)&p_stat_f, g_stat_f);
    cudaGetSymbolAddress((void**)&p_stat_s, g_stat_s);
    cudaGetSymbolAddress((void**)&p_h,      g_h);
    cudaGetSymbolAddress((void**)&p_w2p,    g_w2p);
    cudaGetSymbolAddress((void**)&p_w1p,    g_w1p);
    cudaGetSymbolAddress((void**)&p_b2p,    g_b2p);
    cudaGetSymbolAddress((void**)&p_b1p,    g_b1p);

    // fork
    cudaEventRecord(ev_fork, 0);
    cudaStreamWaitEvent(s2, ev_fork, 0);
    cudaStreamWaitEvent(s3, ev_fork, 0);

    // s2: kNN + tail (independent of GEMM chain)
    knn_kernel<<<MTOT / 256, 256, 3 * NC * sizeof(float), s2>>>(xyz, sxyz);
    tail_kernel<<<(MTOT * 3 + 255) / 256, 256, 0, s2>>>(sxyz, soff, out);
    cudaEventRecord(ev_j2, s2);

    // s3: weight prep (overlaps stats_f), then stats for branch 1
    prep_kernel<<<CIN + COUT + 2, COUT, 0, s3>>>(w2, ln2_g, ln2_b, b2, w1, ln1_g, ln1_b, b1);
    cudaEventRecord(ev_prep, s3);
    stats_kernel<COUT><<<MTOT / 8, 256, 0, s3>>>(sfeats, p_stat_s, MTOT);
    cudaEventRecord(ev_j3, s3);

    // main: stats_f -> gemm2
    stats_kernel<CIN><<<NTOT / 8, 256>>>(feats, p_stat_f, NTOT);
    cudaStreamWaitEvent(0, ev_prep, 0);
    {
        dim3 grid(COUT / 64, NTOT / 128);
        gemm_kernel<CIN, false><<<grid, 256>>>(feats, p_stat_f, p_w2p, p_b2p, p_h);
    }

    // join kNN + stats_s, then gemm1 with fused interp epilogue
    cudaStreamWaitEvent(0, ev_j2, 0);
    cudaStreamWaitEvent(0, ev_j3, 0);
    {
        dim3 grid(COUT / 64, MTOT / 128);
        gemm_kernel<COUT, true><<<grid, 256>>>(sfeats, p_stat_s, p_w1p, p_b1p, out);
    }
}